// round 11
// baseline (speedup 1.0000x reference)
#include <cuda_runtime.h>
#include <cuda_bf16.h>

// CrossAttention collapse: softmax over identical key logits is exactly uniform
// -> y[b,t,:] = v[b,:] -> out[b,t,:] = ((visual@Wv+bv)@Wp + bp)[b,:].
//
// Pipeline:
//   K1  (128 blocks): per 8-wide i-chunk c, vv[b,c] = (visual@Wv+bv)[chunk],
//       then P[c][b][:] = sum_{i in c} vv[b,i]*Wp[i,:]. All global reads
//       (visual, Wv, Wp) prefetched into registers BEFORE any reduction so the
//       three memory latencies overlap.
//   K2a (32 blocks):  row = bp + sum_c P[c]   (2 MB L2 read, no redundancy)
//   K2b (512 blocks): out[b,t,:] = row[b,:]   (pure streaming broadcast)

#define C_DIM 1024
#define B_DIM 4
#define NC    128   // number of i-chunks
#define IC    8     // i per chunk

__device__ float4 g_P[NC][B_DIM][C_DIM / 4];   // 2 MB partial rows
__device__ float4 g_row[B_DIM][C_DIM / 4];     // 16 KB final rows

__device__ __forceinline__ float4 f4add(float4 a, float4 b) {
    return make_float4(a.x + b.x, a.y + b.y, a.z + b.z, a.w + b.w);
}

// ---------------------------------------------------------------------------
// K1: grid = NC blocks, block = 1024.
// Prefetch: visual (via regs->smem), Wv column slice, Wp row slice — all
// issued before the first __syncthreads so DRAM latencies overlap.
// Stage A: vv[b][i0..i0+7]: il = tid&7, s = tid>>3 (128-way k-split).
// Stage B: thread j=tid emits P[c][b][j] from register-resident Wp.
// ---------------------------------------------------------------------------
__global__ void __launch_bounds__(1024) k_part(
    const float* __restrict__ visual, const float* __restrict__ Wv,
    const float* __restrict__ bv,     const float* __restrict__ Wp)
{
    __shared__ float vis[B_DIM * C_DIM];          // 16 KB
    __shared__ float red[32][B_DIM][IC + 1];      // padded vs bank conflicts
    __shared__ float vvsm[B_DIM][IC];
    __shared__ float bvsm[IC];

    const int tid = threadIdx.x;
    const int c   = blockIdx.x;
    const int i0  = c * IC;
    const int il  = tid & 7;
    const int s   = tid >> 3;      // k-slice 0..127
    const int w   = tid >> 5;      // warp 0..31

    // ---- prefetch everything ----
    float visr0 = visual[tid];
    float visr1 = visual[1024 + tid];
    float visr2 = visual[2048 + tid];
    float visr3 = visual[3072 + tid];

    const float* __restrict__ Wcol = Wv + i0 + il;
    float wvr[8];
    #pragma unroll
    for (int kk = 0; kk < 8; ++kk)
        wvr[kk] = __ldg(Wcol + (s * 8 + kk) * C_DIM);

    float wpr[IC];
    #pragma unroll
    for (int q = 0; q < IC; ++q)
        wpr[q] = __ldg(Wp + (i0 + q) * C_DIM + tid);

    if (tid < IC) bvsm[tid] = bv[i0 + tid];

    vis[tid]        = visr0;
    vis[1024 + tid] = visr1;
    vis[2048 + tid] = visr2;
    vis[3072 + tid] = visr3;
    __syncthreads();

    // ---- stage A: chunk of vv ----
    float a0 = 0.f, a1 = 0.f, a2 = 0.f, a3 = 0.f;
    #pragma unroll
    for (int kk = 0; kk < 8; ++kk) {
        const int k = s * 8 + kk;
        const float wv = wvr[kk];
        a0 = fmaf(vis[k],        wv, a0);
        a1 = fmaf(vis[1024 + k], wv, a1);
        a2 = fmaf(vis[2048 + k], wv, a2);
        a3 = fmaf(vis[3072 + k], wv, a3);
    }
    // intra-warp fixed-order reduce (lanes L, L+8, L+16, L+24 share il)
    a0 += __shfl_down_sync(0xffffffffu, a0, 16);
    a1 += __shfl_down_sync(0xffffffffu, a1, 16);
    a2 += __shfl_down_sync(0xffffffffu, a2, 16);
    a3 += __shfl_down_sync(0xffffffffu, a3, 16);
    a0 += __shfl_down_sync(0xffffffffu, a0, 8);
    a1 += __shfl_down_sync(0xffffffffu, a1, 8);
    a2 += __shfl_down_sync(0xffffffffu, a2, 8);
    a3 += __shfl_down_sync(0xffffffffu, a3, 8);
    if ((tid & 31) < 8) {
        red[w][0][il] = a0; red[w][1][il] = a1;
        red[w][2][il] = a2; red[w][3][il] = a3;
    }
    __syncthreads();

    // fixed-order tree over the 32 warps (16*32=512 <= 1024 threads: valid)
    #pragma unroll
    for (int off = 16; off >= 1; off >>= 1) {
        if (tid < off * 32) {
            const int w2 = tid >> 5, r = tid & 31, b = r >> 3, il2 = r & 7;
            red[w2][b][il2] += red[w2 + off][b][il2];
        }
        __syncthreads();
    }
    if (tid < 32) {
        const int b = tid >> 3, il2 = tid & 7;
        vvsm[b][il2] = red[0][b][il2] + bvsm[il2];
    }
    __syncthreads();

    // ---- stage B: partial rows, Wp already in registers ----
    float r0 = 0.f, r1 = 0.f, r2 = 0.f, r3 = 0.f;
    #pragma unroll
    for (int q = 0; q < IC; ++q) {
        const float wp = wpr[q];
        r0 = fmaf(vvsm[0][q], wp, r0);
        r1 = fmaf(vvsm[1][q], wp, r1);
        r2 = fmaf(vvsm[2][q], wp, r2);
        r3 = fmaf(vvsm[3][q], wp, r3);
    }
    float* Pf = reinterpret_cast<float*>(g_P);
    Pf[((c * B_DIM + 0) * C_DIM) + tid] = r0;
    Pf[((c * B_DIM + 1) * C_DIM) + tid] = r1;
    Pf[((c * B_DIM + 2) * C_DIM) + tid] = r2;
    Pf[((c * B_DIM + 3) * C_DIM) + tid] = r3;
}

// ---------------------------------------------------------------------------
// K2a: row[b][j4] = bp[j4] + sum_c P[c][b][j4].
// grid = 32 (b = bid>>3, jg = bid&7), block = 256: j4l = tid&31, cg = tid>>5.
// Each thread sums 16 chunks (independent L2 loads), then a fixed-order
// 3-level smem tree over the 8 c-groups.
// ---------------------------------------------------------------------------
__global__ void __launch_bounds__(256) k_rows(const float* __restrict__ bp)
{
    __shared__ float4 sm[8][32];

    const int tid = threadIdx.x;
    const int b   = blockIdx.x >> 3;
    const int jg  = blockIdx.x & 7;
    const int j4l = tid & 31;
    const int cg  = tid >> 5;
    const int j4  = jg * 32 + j4l;

    float4 acc = make_float4(0.f, 0.f, 0.f, 0.f);
    #pragma unroll
    for (int cc = 0; cc < 16; ++cc)
        acc = f4add(acc, g_P[cg * 16 + cc][b][j4]);
    sm[cg][j4l] = acc;
    __syncthreads();

    #pragma unroll
    for (int off = 4; off >= 1; off >>= 1) {
        if (cg < off)
            sm[cg][j4l] = f4add(sm[cg][j4l], sm[cg + off][j4l]);
        __syncthreads();
    }
    if (cg == 0) {
        const float4 bias = reinterpret_cast<const float4*>(bp)[j4];
        g_row[b][j4] = f4add(sm[0][j4l], bias);
    }
}

// ---------------------------------------------------------------------------
// K2b: out[b][t][:] = row[b][:].
// grid = 512 (b = bid>>7, tbase = (bid&127)*8), block = 256 (c4 = tid).
// One L2-hit row load per thread, 8 fully-coalesced float4 stores.
// ---------------------------------------------------------------------------
__global__ void __launch_bounds__(256) k_bcast(float4* __restrict__ out4)
{
    const int tid   = threadIdx.x;          // c4 0..255
    const int b     = blockIdx.x >> 7;
    const int tbase = (blockIdx.x & 127) * 8;

    const float4 val = __ldg(&g_row[b][tid]);
    const size_t base = ((size_t)(b << 10) + tbase) * 256 + tid;
    #pragma unroll
    for (int i = 0; i < 8; ++i)
        out4[base + (size_t)i * 256] = val;
}

extern "C" void kernel_launch(void* const* d_in, const int* in_sizes, int n_in,
                              void* d_out, int out_size)
{
    const float* visual = (const float*)d_in[1];
    const float* Wv     = (const float*)d_in[6];
    const float* bv     = (const float*)d_in[7];
    const float* Wp     = (const float*)d_in[8];
    const float* bp     = (const float*)d_in[9];

    k_part<<<NC, 1024>>>(visual, Wv, bv, Wp);
    k_rows<<<32, 256>>>(bp);
    k_bcast<<<512, 256>>>(reinterpret_cast<float4*>(d_out));
}